// round 2
// baseline (speedup 1.0000x reference)
#include <cuda_runtime.h>
#include <cstdint>

#define BSZ  256
#define TSEQ 512
#define HIDN 256

// ---- static scratch (no runtime allocation) ----
__device__ float g_xg[(size_t)TSEQ * BSZ * 1024];      // gate preactivations (reused by both layers)
__device__ float g_hist0[(size_t)TSEQ * BSZ * HIDN];   // layer-0 h history
__device__ float g_hist1[(size_t)TSEQ * BSZ * HIDN];   // layer-1 h history
__device__ unsigned g_bar[16];                         // per-batch-group step counters

__global__ void reset_bar() { if (threadIdx.x < 16) g_bar[threadIdx.x] = 0u; }

__device__ __forceinline__ float sigm(float x) { return 1.f / (1.f + __expf(-x)); }
__device__ __forceinline__ float ftanh(float x) {
    float e = __expf(-2.f * fabsf(x));
    return copysignf((1.f - e) / (1.f + e), x);
}

// ---- GEMM: out[m][n] = A_row(m) . W[n] + b1[n] + b2[n], m = t*BSZ + b ----
// XMODE: A_row offset = (b*TSEQ + t)*K  (x is [B,T,IN]); else m*K.
template<int K, bool XMODE>
__global__ void __launch_bounds__(256) gemm_xg(
    const float* __restrict__ A, const float* __restrict__ W,
    const float* __restrict__ b1, const float* __restrict__ b2,
    float* __restrict__ out)
{
    __shared__ float As[32][68];
    __shared__ float Ws[32][132];
    const int m0 = blockIdx.x * 64, n0 = blockIdx.y * 128;
    const int tid = threadIdx.x;
    const int tm = tid >> 4, tn = tid & 15;

    float acc[4][8];
#pragma unroll
    for (int i = 0; i < 4; i++)
#pragma unroll
        for (int j = 0; j < 8; j++) acc[i][j] = 0.f;

    for (int kt = 0; kt < K; kt += 32) {
#pragma unroll
        for (int i = 0; i < 2; i++) {
            int idx = tid + (i << 8);
            int k4 = (idx & 7) << 2, m = idx >> 3;
            int row = m0 + m;
            size_t aoff;
            if (XMODE) { int bb = row & 255, tt = row >> 8; aoff = ((size_t)bb * TSEQ + tt) * K; }
            else       { aoff = (size_t)row * K; }
            float4 v = *reinterpret_cast<const float4*>(A + aoff + kt + k4);
            As[k4+0][m]=v.x; As[k4+1][m]=v.y; As[k4+2][m]=v.z; As[k4+3][m]=v.w;
        }
#pragma unroll
        for (int i = 0; i < 4; i++) {
            int idx = tid + (i << 8);
            int k4 = (idx & 7) << 2, n = idx >> 3;
            float4 v = *reinterpret_cast<const float4*>(W + (size_t)(n0 + n) * K + kt + k4);
            Ws[k4+0][n]=v.x; Ws[k4+1][n]=v.y; Ws[k4+2][n]=v.z; Ws[k4+3][n]=v.w;
        }
        __syncthreads();
#pragma unroll
        for (int k = 0; k < 32; k++) {
            float a[4], w[8];
            *reinterpret_cast<float4*>(&a[0]) = *reinterpret_cast<const float4*>(&As[k][tm << 2]);
            *reinterpret_cast<float4*>(&w[0]) = *reinterpret_cast<const float4*>(&Ws[k][tn << 3]);
            *reinterpret_cast<float4*>(&w[4]) = *reinterpret_cast<const float4*>(&Ws[k][(tn << 3) + 4]);
#pragma unroll
            for (int i = 0; i < 4; i++)
#pragma unroll
                for (int j = 0; j < 8; j++) acc[i][j] += a[i] * w[j];
        }
        __syncthreads();
    }

    float bv[8];
#pragma unroll
    for (int j = 0; j < 8; j++) bv[j] = b1[n0 + (tn << 3) + j] + b2[n0 + (tn << 3) + j];
#pragma unroll
    for (int i = 0; i < 4; i++) {
        size_t ro = (size_t)(m0 + (tm << 2) + i) * 1024 + n0 + (tn << 3);
        float4 o0 = make_float4(acc[i][0]+bv[0], acc[i][1]+bv[1], acc[i][2]+bv[2], acc[i][3]+bv[3]);
        float4 o1 = make_float4(acc[i][4]+bv[4], acc[i][5]+bv[5], acc[i][6]+bv[6], acc[i][7]+bv[7]);
        *reinterpret_cast<float4*>(out + ro)     = o0;
        *reinterpret_cast<float4*>(out + ro + 4) = o1;
    }
}

// ---- persistent LSTM recurrence: 128 CTAs = 16 batch-groups x 8 n-groups ----
__global__ void __launch_bounds__(256, 1) rec_kernel(
    const float* __restrict__ xg, const float* __restrict__ Whh,
    float* __restrict__ hist)
{
    extern __shared__ float sm[];
    float* Wsh = sm;            // 256k x 128c = 32768 floats
    float* hsh = Wsh + 32768;   // 16 x 260    =  4160
    float* red = hsh + 4160;    // 4 x 16 x128 =  8192

    const int bi = blockIdx.x >> 3, ni = blockIdx.x & 7;
    const int b0 = bi << 4, n0 = ni << 5;
    const int tid = threadIdx.x;
    const int kg = tid >> 6, cid = tid & 63;
    const int bb0 = (cid >> 4) << 2;       // 0,4,8,12
    const int c0  = (cid & 15) << 3;       // 0..120

    // resident weight slice: Wsh[k*128 + c], c = g*32+nn <-> W_hh row g*256+n0+nn
    for (int idx = tid; idx < 8192; idx += 256) {
        int kq = idx & 63, c = idx >> 6;
        int g = c >> 5, nn = c & 31;
        float4 v = *reinterpret_cast<const float4*>(
            Whh + (size_t)((g << 8) + n0 + nn) * HIDN + (kq << 2));
        int k = kq << 2;
        Wsh[(k+0)*128+c]=v.x; Wsh[(k+1)*128+c]=v.y; Wsh[(k+2)*128+c]=v.z; Wsh[(k+3)*128+c]=v.w;
    }
    __syncthreads();

    volatile unsigned* bar = (volatile unsigned*)(g_bar + bi);
    float creg[2] = {0.f, 0.f};

    for (int t = 0; t < TSEQ; t++) {
        float acc[4][8];
#pragma unroll
        for (int i = 0; i < 4; i++)
#pragma unroll
            for (int j = 0; j < 8; j++) acc[i][j] = 0.f;

        if (t > 0) {
            if (tid == 0) {
                unsigned tgt = (unsigned)(t << 3);
                while (*bar < tgt) __nanosleep(32);
            }
            __syncthreads();
            __threadfence();
            // stage h(t-1) for our 16 batches
            const float* hp = hist + ((size_t)(t - 1) * BSZ + b0) * HIDN;
#pragma unroll
            for (int i = 0; i < 4; i++) {
                int idx = tid + (i << 8);
                int b = idx >> 6, k4 = (idx & 63) << 2;
                float4 v = *reinterpret_cast<const float4*>(hp + (b << 8) + k4);
                *reinterpret_cast<float4*>(&hsh[b * 260 + k4]) = v;
            }
            __syncthreads();

            const float* hpL = hsh + bb0 * 260 + (kg << 6);
            const float* wp  = Wsh + ((kg << 6) * 128) + c0;
#pragma unroll 8
            for (int k = 0; k < 64; k++) {
                float h0v = hpL[k], h1v = hpL[260 + k], h2v = hpL[520 + k], h3v = hpL[780 + k];
                float w[8];
                *reinterpret_cast<float4*>(&w[0]) = *reinterpret_cast<const float4*>(wp);
                *reinterpret_cast<float4*>(&w[4]) = *reinterpret_cast<const float4*>(wp + 4);
                wp += 128;
#pragma unroll
                for (int j = 0; j < 8; j++) {
                    acc[0][j] += h0v * w[j];
                    acc[1][j] += h1v * w[j];
                    acc[2][j] += h2v * w[j];
                    acc[3][j] += h3v * w[j];
                }
            }
        }

        // k-split partials
#pragma unroll
        for (int i = 0; i < 4; i++) {
            float* rp = red + (kg << 11) + (bb0 + i) * 128 + c0;
            *reinterpret_cast<float4*>(rp)     = make_float4(acc[i][0], acc[i][1], acc[i][2], acc[i][3]);
            *reinterpret_cast<float4*>(rp + 4) = make_float4(acc[i][4], acc[i][5], acc[i][6], acc[i][7]);
        }
        __syncthreads();

        // epilogue: 512 (b,nn) cells, 2 per thread; c lives in registers
        const float* xgp = xg + ((size_t)t * BSZ + b0) * 1024;
        float* ho = hist + ((size_t)t * BSZ + b0) * HIDN;
#pragma unroll
        for (int pp = 0; pp < 2; pp++) {
            int p = (tid << 1) + pp;
            int b = p >> 5, nn = p & 31;
            int cb = b * 128 + nn;
            float gv[4];
#pragma unroll
            for (int g = 0; g < 4; g++) {
                int c = cb + (g << 5);
                gv[g] = red[c] + red[c + 2048] + red[c + 4096] + red[c + 6144]
                      + xgp[(b << 10) + (g << 8) + n0 + nn];
            }
            float cn = sigm(gv[1]) * creg[pp] + sigm(gv[0]) * ftanh(gv[2]);
            creg[pp] = cn;
            ho[(b << 8) + n0 + nn] = sigm(gv[3]) * ftanh(cn);
        }
        __threadfence();
        __syncthreads();
        if (tid == 0) atomicAdd(g_bar + bi, 1u);
    }
}

// ---- head: out[b] = h_last[b] . W_head + b_head ----
__global__ void head_kernel(const float* __restrict__ Wh, const float* __restrict__ bh,
                            float* __restrict__ out)
{
    __shared__ float rs[8];
    int b = blockIdx.x, tid = threadIdx.x;
    float v = g_hist1[((size_t)(TSEQ - 1) * BSZ + b) * HIDN + tid] * Wh[tid];
#pragma unroll
    for (int o = 16; o > 0; o >>= 1) v += __shfl_down_sync(0xffffffffu, v, o);
    if ((tid & 31) == 0) rs[tid >> 5] = v;
    __syncthreads();
    if (tid < 8) {
        float s = rs[tid];
#pragma unroll
        for (int o = 4; o > 0; o >>= 1) s += __shfl_down_sync(0xffu, s, o);
        if (tid == 0) out[b] = s + bh[0];
    }
}

extern "C" void kernel_launch(void* const* d_in, const int* in_sizes, int n_in,
                              void* d_out, int out_size)
{
    const float* x      = (const float*)d_in[0];
    const float* W_ih0  = (const float*)d_in[1];
    const float* W_hh0  = (const float*)d_in[2];
    const float* b_ih0  = (const float*)d_in[3];
    const float* b_hh0  = (const float*)d_in[4];
    const float* W_ih1  = (const float*)d_in[5];
    const float* W_hh1  = (const float*)d_in[6];
    const float* b_ih1  = (const float*)d_in[7];
    const float* b_hh1  = (const float*)d_in[8];
    const float* W_head = (const float*)d_in[9];
    const float* b_head = (const float*)d_in[10];
    float* out = (float*)d_out;

    void *pxg, *ph0, *ph1;
    cudaGetSymbolAddress(&pxg, g_xg);
    cudaGetSymbolAddress(&ph0, g_hist0);
    cudaGetSymbolAddress(&ph1, g_hist1);
    float* xg = (float*)pxg; float* h0 = (float*)ph0; float* h1 = (float*)ph1;

    const int SMEM = 45120 * 4;  // 180480 B
    cudaFuncSetAttribute(rec_kernel, cudaFuncAttributeMaxDynamicSharedMemorySize, SMEM);

    dim3 gg(2048, 8);
    gemm_xg<64,  true ><<<gg, 256>>>(x,  W_ih0, b_ih0, b_hh0, xg);
    reset_bar<<<1, 32>>>();
    rec_kernel<<<128, 256, SMEM>>>(xg, W_hh0, h0);
    gemm_xg<256, false><<<gg, 256>>>(h0, W_ih1, b_ih1, b_hh1, xg);
    reset_bar<<<1, 32>>>();
    rec_kernel<<<128, 256, SMEM>>>(xg, W_hh1, h1);
    head_kernel<<<256, 256>>>(W_head, b_head, out);
}

// round 3
// speedup vs baseline: 1.1131x; 1.1131x over previous
#include <cuda_runtime.h>
#include <cstdint>

#define BSZ  256
#define TSEQ 512
#define HIDN 256

typedef unsigned long long ull;

// ---- static scratch ----
__device__ float g_xg[(size_t)TSEQ * BSZ * 1024];
__device__ float g_hist0[(size_t)TSEQ * BSZ * HIDN];
__device__ float g_hist1[(size_t)TSEQ * BSZ * HIDN];
__device__ unsigned g_bar[16];

__global__ void reset_bar() { if (threadIdx.x < 16) g_bar[threadIdx.x] = 0u; }

__device__ __forceinline__ float sigm(float x) { return 1.f / (1.f + __expf(-x)); }
__device__ __forceinline__ float ftanh(float x) {
    float e = __expf(-2.f * fabsf(x));
    return copysignf((1.f - e) / (1.f + e), x);
}

// ---- packed fp32x2 helpers (Blackwell FFMA2) ----
__device__ __forceinline__ ull ffma2(ull a, ull b, ull c) {
    ull d; asm("fma.rn.f32x2 %0, %1, %2, %3;" : "=l"(d) : "l"(a), "l"(b), "l"(c)); return d;
}
__device__ __forceinline__ ull dup2(float x) {
    ull r; asm("mov.b64 %0, {%1, %1};" : "=l"(r) : "f"(x)); return r;
}
__device__ __forceinline__ float2 unpk(ull v) {
    float2 f; asm("mov.b64 {%0, %1}, %2;" : "=f"(f.x), "=f"(f.y) : "l"(v)); return f;
}

// ---- GEMM: out[m][n] = A_row(m) . W[n] + b1[n] + b2[n], m = t*BSZ + b ----
// 128x128 block tile, k-tile 16, 256 threads, 8x8 per thread, f32x2 math.
template<int K, bool XMODE>
__global__ void __launch_bounds__(256, 2) gemm_xg(
    const float* __restrict__ A, const float* __restrict__ W,
    const float* __restrict__ b1, const float* __restrict__ b2,
    float* __restrict__ out)
{
    __shared__ float As[16][132];
    __shared__ float Ws[16][132];
    const int m0 = blockIdx.x * 128, n0 = blockIdx.y * 128;
    const int tid = threadIdx.x;
    const int tm = tid >> 4, tn = tid & 15;

    ull acc[8][4];
#pragma unroll
    for (int i = 0; i < 8; i++)
#pragma unroll
        for (int j = 0; j < 4; j++) acc[i][j] = 0ull;

    for (int kt = 0; kt < K; kt += 16) {
#pragma unroll
        for (int i = 0; i < 2; i++) {
            int idx = tid + (i << 8);              // 0..511
            int rr = idx >> 2, kq = idx & 3;
            int row = m0 + rr;
            size_t aoff;
            if (XMODE) { aoff = ((size_t)(row & 255) * TSEQ + (row >> 8)) * K; }
            else       { aoff = (size_t)row * K; }
            float4 v = *reinterpret_cast<const float4*>(A + aoff + kt + (kq << 2));
            int k = kq << 2;
            As[k+0][rr]=v.x; As[k+1][rr]=v.y; As[k+2][rr]=v.z; As[k+3][rr]=v.w;
        }
#pragma unroll
        for (int i = 0; i < 2; i++) {
            int idx = tid + (i << 8);
            int rr = idx >> 2, kq = idx & 3;
            float4 v = *reinterpret_cast<const float4*>(W + (size_t)(n0 + rr) * K + kt + (kq << 2));
            int k = kq << 2;
            Ws[k+0][rr]=v.x; Ws[k+1][rr]=v.y; Ws[k+2][rr]=v.z; Ws[k+3][rr]=v.w;
        }
        __syncthreads();
#pragma unroll
        for (int k = 0; k < 16; k++) {
            float a[8];
            *reinterpret_cast<float4*>(&a[0]) = *reinterpret_cast<const float4*>(&As[k][tm << 3]);
            *reinterpret_cast<float4*>(&a[4]) = *reinterpret_cast<const float4*>(&As[k][(tm << 3) + 4]);
            ulonglong2 wa = *reinterpret_cast<const ulonglong2*>(&Ws[k][tn << 3]);
            ulonglong2 wb = *reinterpret_cast<const ulonglong2*>(&Ws[k][(tn << 3) + 4]);
            ull w2[4] = {wa.x, wa.y, wb.x, wb.y};
#pragma unroll
            for (int i = 0; i < 8; i++) {
                ull ad = dup2(a[i]);
#pragma unroll
                for (int j = 0; j < 4; j++) acc[i][j] = ffma2(ad, w2[j], acc[i][j]);
            }
        }
        __syncthreads();
    }

    float bv[8];
#pragma unroll
    for (int j = 0; j < 8; j++) bv[j] = b1[n0 + (tn << 3) + j] + b2[n0 + (tn << 3) + j];
#pragma unroll
    for (int i = 0; i < 8; i++) {
        size_t ro = (size_t)(m0 + (tm << 3) + i) * 1024 + n0 + (tn << 3);
        float2 p0 = unpk(acc[i][0]), p1 = unpk(acc[i][1]);
        float2 p2 = unpk(acc[i][2]), p3 = unpk(acc[i][3]);
        float4 o0 = make_float4(p0.x+bv[0], p0.y+bv[1], p1.x+bv[2], p1.y+bv[3]);
        float4 o1 = make_float4(p2.x+bv[4], p2.y+bv[5], p3.x+bv[6], p3.y+bv[7]);
        *reinterpret_cast<float4*>(out + ro)     = o0;
        *reinterpret_cast<float4*>(out + ro + 4) = o1;
    }
}

// ---- persistent LSTM recurrence: 128 CTAs = 16 batch-groups x 8 n-groups ----
__global__ void __launch_bounds__(256, 1) rec_kernel(
    const float* __restrict__ xg, const float* __restrict__ Whh,
    float* __restrict__ hist)
{
    extern __shared__ float sm[];
    float* Wsh = sm;            // 256k x 128c = 32768
    float* hsh = Wsh + 32768;   // 16 x 260    =  4160
    float* red = hsh + 4160;    // 4 x 16 x128 =  8192

    const int bi = blockIdx.x >> 3, ni = blockIdx.x & 7;
    const int b0 = bi << 4, n0 = ni << 5;
    const int tid = threadIdx.x;
    const int kg = tid >> 6, cid = tid & 63;
    const int bb0 = (cid >> 4) << 2;
    const int c0  = (cid & 15) << 3;

    for (int idx = tid; idx < 8192; idx += 256) {
        int kq = idx & 63, c = idx >> 6;
        int g = c >> 5, nn = c & 31;
        float4 v = *reinterpret_cast<const float4*>(
            Whh + (size_t)((g << 8) + n0 + nn) * HIDN + (kq << 2));
        int k = kq << 2;
        Wsh[(k+0)*128+c]=v.x; Wsh[(k+1)*128+c]=v.y; Wsh[(k+2)*128+c]=v.z; Wsh[(k+3)*128+c]=v.w;
    }
    __syncthreads();

    volatile unsigned* bar = (volatile unsigned*)(g_bar + bi);
    float creg[2] = {0.f, 0.f};

    for (int t = 0; t < TSEQ; t++) {
        ull acc2[4][4];
#pragma unroll
        for (int i = 0; i < 4; i++)
#pragma unroll
            for (int j = 0; j < 4; j++) acc2[i][j] = 0ull;

        if (t > 0) {
            if (tid == 0) {
                unsigned tgt = (unsigned)(t << 3);
                while (*bar < tgt) __nanosleep(32);
            }
            __syncthreads();
            __threadfence();
            const float* hp = hist + ((size_t)(t - 1) * BSZ + b0) * HIDN;
#pragma unroll
            for (int i = 0; i < 4; i++) {
                int idx = tid + (i << 8);
                int b = idx >> 6, k4 = (idx & 63) << 2;
                float4 v = *reinterpret_cast<const float4*>(hp + (b << 8) + k4);
                *reinterpret_cast<float4*>(&hsh[b * 260 + k4]) = v;
            }
            __syncthreads();

            const float* hpL = hsh + bb0 * 260 + (kg << 6);
            const float* wp  = Wsh + ((kg << 6) * 128) + c0;
#pragma unroll 8
            for (int k = 0; k < 64; k++) {
                ull hd0 = dup2(hpL[k]);
                ull hd1 = dup2(hpL[260 + k]);
                ull hd2 = dup2(hpL[520 + k]);
                ull hd3 = dup2(hpL[780 + k]);
                ulonglong2 wa = *reinterpret_cast<const ulonglong2*>(wp);
                ulonglong2 wb = *reinterpret_cast<const ulonglong2*>(wp + 4);
                wp += 128;
                ull w2[4] = {wa.x, wa.y, wb.x, wb.y};
#pragma unroll
                for (int j = 0; j < 4; j++) {
                    acc2[0][j] = ffma2(hd0, w2[j], acc2[0][j]);
                    acc2[1][j] = ffma2(hd1, w2[j], acc2[1][j]);
                    acc2[2][j] = ffma2(hd2, w2[j], acc2[2][j]);
                    acc2[3][j] = ffma2(hd3, w2[j], acc2[3][j]);
                }
            }
        }

#pragma unroll
        for (int i = 0; i < 4; i++) {
            float* rp = red + (kg << 11) + (bb0 + i) * 128 + c0;
            *reinterpret_cast<ulonglong2*>(rp)     = make_ulonglong2(acc2[i][0], acc2[i][1]);
            *reinterpret_cast<ulonglong2*>(rp + 4) = make_ulonglong2(acc2[i][2], acc2[i][3]);
        }
        __syncthreads();

        const float* xgp = xg + ((size_t)t * BSZ + b0) * 1024;
        float* ho = hist + ((size_t)t * BSZ + b0) * HIDN;
#pragma unroll
        for (int pp = 0; pp < 2; pp++) {
            int p = (tid << 1) + pp;
            int b = p >> 5, nn = p & 31;
            int cb = b * 128 + nn;
            float gv[4];
#pragma unroll
            for (int g = 0; g < 4; g++) {
                int c = cb + (g << 5);
                gv[g] = red[c] + red[c + 2048] + red[c + 4096] + red[c + 6144]
                      + xgp[(b << 10) + (g << 8) + n0 + nn];
            }
            float cn = sigm(gv[1]) * creg[pp] + sigm(gv[0]) * ftanh(gv[2]);
            creg[pp] = cn;
            ho[(b << 8) + n0 + nn] = sigm(gv[3]) * ftanh(cn);
        }
        __threadfence();
        __syncthreads();
        if (tid == 0) atomicAdd(g_bar + bi, 1u);
    }
}

// ---- head ----
__global__ void head_kernel(const float* __restrict__ Wh, const float* __restrict__ bh,
                            float* __restrict__ out)
{
    __shared__ float rs[8];
    int b = blockIdx.x, tid = threadIdx.x;
    float v = g_hist1[((size_t)(TSEQ - 1) * BSZ + b) * HIDN + tid] * Wh[tid];
#pragma unroll
    for (int o = 16; o > 0; o >>= 1) v += __shfl_down_sync(0xffffffffu, v, o);
    if ((tid & 31) == 0) rs[tid >> 5] = v;
    __syncthreads();
    if (tid < 8) {
        float s = rs[tid];
#pragma unroll
        for (int o = 4; o > 0; o >>= 1) s += __shfl_down_sync(0xffu, s, o);
        if (tid == 0) out[b] = s + bh[0];
    }
}

extern "C" void kernel_launch(void* const* d_in, const int* in_sizes, int n_in,
                              void* d_out, int out_size)
{
    const float* x      = (const float*)d_in[0];
    const float* W_ih0  = (const float*)d_in[1];
    const float* W_hh0  = (const float*)d_in[2];
    const float* b_ih0  = (const float*)d_in[3];
    const float* b_hh0  = (const float*)d_in[4];
    const float* W_ih1  = (const float*)d_in[5];
    const float* W_hh1  = (const float*)d_in[6];
    const float* b_ih1  = (const float*)d_in[7];
    const float* b_hh1  = (const float*)d_in[8];
    const float* W_head = (const float*)d_in[9];
    const float* b_head = (const float*)d_in[10];
    float* out = (float*)d_out;

    void *pxg, *ph0, *ph1;
    cudaGetSymbolAddress(&pxg, g_xg);
    cudaGetSymbolAddress(&ph0, g_hist0);
    cudaGetSymbolAddress(&ph1, g_hist1);
    float* xg = (float*)pxg; float* h0 = (float*)ph0; float* h1 = (float*)ph1;

    const int SMEM = 45120 * 4;
    cudaFuncSetAttribute(rec_kernel, cudaFuncAttributeMaxDynamicSharedMemorySize, SMEM);

    dim3 gg(1024, 8);
    gemm_xg<64,  true ><<<gg, 256>>>(x,  W_ih0, b_ih0, b_hh0, xg);
    reset_bar<<<1, 32>>>();
    rec_kernel<<<128, 256, SMEM>>>(xg, W_hh0, h0);
    gemm_xg<256, false><<<gg, 256>>>(h0, W_ih1, b_ih1, b_hh1, xg);
    reset_bar<<<1, 32>>>();
    rec_kernel<<<128, 256, SMEM>>>(xg, W_hh1, h1);
    head_kernel<<<256, 256>>>(W_head, b_head, out);
}

// round 4
// speedup vs baseline: 1.1365x; 1.0210x over previous
#include <cuda_runtime.h>
#include <cstdint>

#define BSZ  256
#define TSEQ 512
#define HIDN 256

typedef unsigned long long ull;

// ---- static scratch ----
__device__ float g_xg[(size_t)TSEQ * BSZ * 1024];
__device__ float g_hist0[(size_t)TSEQ * BSZ * HIDN];
__device__ float g_hist1[(size_t)TSEQ * BSZ * HIDN];
__device__ unsigned g_bar[16];

__global__ void reset_bar() { if (threadIdx.x < 16) g_bar[threadIdx.x] = 0u; }

__device__ __forceinline__ float sigm(float x) { return 1.f / (1.f + __expf(-x)); }
__device__ __forceinline__ float ftanh(float x) {
    float e = __expf(-2.f * fabsf(x));
    return copysignf((1.f - e) / (1.f + e), x);
}

// ---- packed fp32x2 (Blackwell FFMA2) ----
__device__ __forceinline__ ull ffma2(ull a, ull b, ull c) {
    ull d; asm("fma.rn.f32x2 %0, %1, %2, %3;" : "=l"(d) : "l"(a), "l"(b), "l"(c)); return d;
}
__device__ __forceinline__ ull dup2(float x) {
    ull r; asm("mov.b64 %0, {%1, %1};" : "=l"(r) : "f"(x)); return r;
}
__device__ __forceinline__ float2 unpk(ull v) {
    float2 f; asm("mov.b64 {%0, %1}, %2;" : "=f"(f.x), "=f"(f.y) : "l"(v)); return f;
}

// ---- scoped sync primitives (no L1-flushing membar.gl) ----
__device__ __forceinline__ unsigned ld_acq(const unsigned* p) {
    unsigned v; asm volatile("ld.acquire.gpu.global.b32 %0, [%1];" : "=r"(v) : "l"(p)); return v;
}
__device__ __forceinline__ void red_rel_add(unsigned* p, unsigned v) {
    asm volatile("red.release.gpu.global.add.u32 [%0], %1;" :: "l"(p), "r"(v) : "memory");
}

// ---- GEMM: out[m][n] = A_row(m) . W[n] + b1[n] + b2[n], m = t*BSZ + b ----
template<int K, bool XMODE>
__global__ void __launch_bounds__(256, 2) gemm_xg(
    const float* __restrict__ A, const float* __restrict__ W,
    const float* __restrict__ b1, const float* __restrict__ b2,
    float* __restrict__ out)
{
    __shared__ float As[16][132];
    __shared__ float Ws[16][132];
    const int m0 = blockIdx.x * 128, n0 = blockIdx.y * 128;
    const int tid = threadIdx.x;
    const int tm = tid >> 4, tn = tid & 15;

    ull acc[8][4];
#pragma unroll
    for (int i = 0; i < 8; i++)
#pragma unroll
        for (int j = 0; j < 4; j++) acc[i][j] = 0ull;

    for (int kt = 0; kt < K; kt += 16) {
#pragma unroll
        for (int i = 0; i < 2; i++) {
            int idx = tid + (i << 8);
            int rr = idx >> 2, kq = idx & 3;
            int row = m0 + rr;
            size_t aoff;
            if (XMODE) { aoff = ((size_t)(row & 255) * TSEQ + (row >> 8)) * K; }
            else       { aoff = (size_t)row * K; }
            float4 v = *reinterpret_cast<const float4*>(A + aoff + kt + (kq << 2));
            int k = kq << 2;
            As[k+0][rr]=v.x; As[k+1][rr]=v.y; As[k+2][rr]=v.z; As[k+3][rr]=v.w;
        }
#pragma unroll
        for (int i = 0; i < 2; i++) {
            int idx = tid + (i << 8);
            int rr = idx >> 2, kq = idx & 3;
            float4 v = *reinterpret_cast<const float4*>(W + (size_t)(n0 + rr) * K + kt + (kq << 2));
            int k = kq << 2;
            Ws[k+0][rr]=v.x; Ws[k+1][rr]=v.y; Ws[k+2][rr]=v.z; Ws[k+3][rr]=v.w;
        }
        __syncthreads();
#pragma unroll
        for (int k = 0; k < 16; k++) {
            float a[8];
            *reinterpret_cast<float4*>(&a[0]) = *reinterpret_cast<const float4*>(&As[k][tm << 3]);
            *reinterpret_cast<float4*>(&a[4]) = *reinterpret_cast<const float4*>(&As[k][(tm << 3) + 4]);
            ulonglong2 wa = *reinterpret_cast<const ulonglong2*>(&Ws[k][tn << 3]);
            ulonglong2 wb = *reinterpret_cast<const ulonglong2*>(&Ws[k][(tn << 3) + 4]);
            ull w2[4] = {wa.x, wa.y, wb.x, wb.y};
#pragma unroll
            for (int i = 0; i < 8; i++) {
                ull ad = dup2(a[i]);
#pragma unroll
                for (int j = 0; j < 4; j++) acc[i][j] = ffma2(ad, w2[j], acc[i][j]);
            }
        }
        __syncthreads();
    }

    float bv[8];
#pragma unroll
    for (int j = 0; j < 8; j++) bv[j] = b1[n0 + (tn << 3) + j] + b2[n0 + (tn << 3) + j];
#pragma unroll
    for (int i = 0; i < 8; i++) {
        size_t ro = (size_t)(m0 + (tm << 3) + i) * 1024 + n0 + (tn << 3);
        float2 p0 = unpk(acc[i][0]), p1 = unpk(acc[i][1]);
        float2 p2 = unpk(acc[i][2]), p3 = unpk(acc[i][3]);
        *reinterpret_cast<float4*>(out + ro)     = make_float4(p0.x+bv[0], p0.y+bv[1], p1.x+bv[2], p1.y+bv[3]);
        *reinterpret_cast<float4*>(out + ro + 4) = make_float4(p2.x+bv[4], p2.y+bv[5], p3.x+bv[6], p3.y+bv[7]);
    }
}

// ---- persistent LSTM recurrence: 128 CTAs = 16 batch-groups x 8 n-groups ----
// SMEM: W slice 128KB, dup-h staging 33.3KB, k-split reduction 32KB  (~197KB)
__global__ void __launch_bounds__(256, 1) rec_kernel(
    const float* __restrict__ xg, const float* __restrict__ Whh,
    float* __restrict__ hist)
{
    extern __shared__ float sm[];
    float* Wsh = sm;            // 32768 floats
    float* hsh = Wsh + 32768;   // 16 x 520 (h duplicated pairs) = 8320
    float* red = hsh + 8320;    // 4 x 16 x 128 = 8192

    const int bi = blockIdx.x >> 3, ni = blockIdx.x & 7;
    const int b0 = bi << 4, n0 = ni << 5;
    const int tid = threadIdx.x;
    const int kg = tid >> 6, cid = tid & 63;
    const int bb0 = (cid >> 4) << 2;
    const int c0  = (cid & 15) << 3;

    for (int idx = tid; idx < 8192; idx += 256) {
        int kq = idx & 63, c = idx >> 6;
        int g = c >> 5, nn = c & 31;
        float4 v = *reinterpret_cast<const float4*>(
            Whh + (size_t)((g << 8) + n0 + nn) * HIDN + (kq << 2));
        int k = kq << 2;
        Wsh[(k+0)*128+c]=v.x; Wsh[(k+1)*128+c]=v.y; Wsh[(k+2)*128+c]=v.z; Wsh[(k+3)*128+c]=v.w;
    }
    __syncthreads();

    // epilogue cell mapping (2 cells per thread)
    const int p0i = tid << 1;
    const int eb0 = p0i >> 5,  enn0 = p0i & 31;
    const int eb1 = (p0i+1) >> 5, enn1 = (p0i+1) & 31;

    float creg[2] = {0.f, 0.f};

    for (int t = 0; t < TSEQ; t++) {
        // ---- prefetch gate preactivations (independent of h) ----
        const float* xgp = xg + ((size_t)t * BSZ + b0) * 1024;
        float xv0[4], xv1[4];
#pragma unroll
        for (int g = 0; g < 4; g++) {
            xv0[g] = __ldg(xgp + (eb0 << 10) + (g << 8) + n0 + enn0);
            xv1[g] = __ldg(xgp + (eb1 << 10) + (g << 8) + n0 + enn1);
        }

        ull acc2[4][4];
#pragma unroll
        for (int i = 0; i < 4; i++)
#pragma unroll
            for (int j = 0; j < 4; j++) acc2[i][j] = 0ull;

        if (t > 0) {
            // all threads acquire-poll: each thread's later loads are ordered
            const unsigned tgt = (unsigned)(t << 3);
            while (ld_acq(g_bar + bi) < tgt) {}

            // stage h(t-1) duplicated: hsh[b*520 + 2k] = hsh[..+1] = h[b][k]
            const float* hp = hist + ((size_t)(t - 1) * BSZ + b0) * HIDN;
#pragma unroll
            for (int i = 0; i < 4; i++) {
                int idx = tid + (i << 8);
                int b = idx >> 6, k4 = (idx & 63) << 2;
                float4 v = *reinterpret_cast<const float4*>(hp + (b << 8) + k4);
                float* dst = hsh + b * 520 + (k4 << 1);
                *reinterpret_cast<float4*>(dst)     = make_float4(v.x, v.x, v.y, v.y);
                *reinterpret_cast<float4*>(dst + 4) = make_float4(v.z, v.z, v.w, v.w);
            }
            __syncthreads();

            const float* hpL = hsh + bb0 * 520 + (kg << 7);
            const float* wp  = Wsh + ((kg << 6) * 128) + c0;
#pragma unroll 8
            for (int k = 0; k < 64; k++) {
                ull hd0 = *reinterpret_cast<const ull*>(hpL + (k << 1));
                ull hd1 = *reinterpret_cast<const ull*>(hpL +  520 + (k << 1));
                ull hd2 = *reinterpret_cast<const ull*>(hpL + 1040 + (k << 1));
                ull hd3 = *reinterpret_cast<const ull*>(hpL + 1560 + (k << 1));
                ulonglong2 wa = *reinterpret_cast<const ulonglong2*>(wp);
                ulonglong2 wb = *reinterpret_cast<const ulonglong2*>(wp + 4);
                wp += 128;
                ull w2[4] = {wa.x, wa.y, wb.x, wb.y};
#pragma unroll
                for (int j = 0; j < 4; j++) {
                    acc2[0][j] = ffma2(hd0, w2[j], acc2[0][j]);
                    acc2[1][j] = ffma2(hd1, w2[j], acc2[1][j]);
                    acc2[2][j] = ffma2(hd2, w2[j], acc2[2][j]);
                    acc2[3][j] = ffma2(hd3, w2[j], acc2[3][j]);
                }
            }
        }

        // k-split partials
#pragma unroll
        for (int i = 0; i < 4; i++) {
            float* rp = red + (kg << 11) + (bb0 + i) * 128 + c0;
            *reinterpret_cast<ulonglong2*>(rp)     = make_ulonglong2(acc2[i][0], acc2[i][1]);
            *reinterpret_cast<ulonglong2*>(rp + 4) = make_ulonglong2(acc2[i][2], acc2[i][3]);
        }
        __syncthreads();

        // epilogue (c in registers)
        float* ho = hist + ((size_t)t * BSZ + b0) * HIDN;
        {
            int cb = eb0 * 128 + enn0;
            float gv[4];
#pragma unroll
            for (int g = 0; g < 4; g++) {
                int c = cb + (g << 5);
                gv[g] = red[c] + red[c + 2048] + red[c + 4096] + red[c + 6144] + xv0[g];
            }
            float cn = sigm(gv[1]) * creg[0] + sigm(gv[0]) * ftanh(gv[2]);
            creg[0] = cn;
            ho[(eb0 << 8) + n0 + enn0] = sigm(gv[3]) * ftanh(cn);
        }
        {
            int cb = eb1 * 128 + enn1;
            float gv[4];
#pragma unroll
            for (int g = 0; g < 4; g++) {
                int c = cb + (g << 5);
                gv[g] = red[c] + red[c + 2048] + red[c + 4096] + red[c + 6144] + xv1[g];
            }
            float cn = sigm(gv[1]) * creg[1] + sigm(gv[0]) * ftanh(gv[2]);
            creg[1] = cn;
            ho[(eb1 << 8) + n0 + enn1] = sigm(gv[3]) * ftanh(cn);
        }
        __syncthreads();                       // all h stores + red reads done
        if (tid == 0) red_rel_add(g_bar + bi, 1u);   // release: publishes the CTA's h
    }
}

// ---- head ----
__global__ void head_kernel(const float* __restrict__ Wh, const float* __restrict__ bh,
                            float* __restrict__ out)
{
    __shared__ float rs[8];
    int b = blockIdx.x, tid = threadIdx.x;
    float v = g_hist1[((size_t)(TSEQ - 1) * BSZ + b) * HIDN + tid] * Wh[tid];
#pragma unroll
    for (int o = 16; o > 0; o >>= 1) v += __shfl_down_sync(0xffffffffu, v, o);
    if ((tid & 31) == 0) rs[tid >> 5] = v;
    __syncthreads();
    if (tid < 8) {
        float s = rs[tid];
#pragma unroll
        for (int o = 4; o > 0; o >>= 1) s += __shfl_down_sync(0xffu, s, o);
        if (tid == 0) out[b] = s + bh[0];
    }
}

extern "C" void kernel_launch(void* const* d_in, const int* in_sizes, int n_in,
                              void* d_out, int out_size)
{
    const float* x      = (const float*)d_in[0];
    const float* W_ih0  = (const float*)d_in[1];
    const float* W_hh0  = (const float*)d_in[2];
    const float* b_ih0  = (const float*)d_in[3];
    const float* b_hh0  = (const float*)d_in[4];
    const float* W_ih1  = (const float*)d_in[5];
    const float* W_hh1  = (const float*)d_in[6];
    const float* b_ih1  = (const float*)d_in[7];
    const float* b_hh1  = (const float*)d_in[8];
    const float* W_head = (const float*)d_in[9];
    const float* b_head = (const float*)d_in[10];
    float* out = (float*)d_out;

    void *pxg, *ph0, *ph1;
    cudaGetSymbolAddress(&pxg, g_xg);
    cudaGetSymbolAddress(&ph0, g_hist0);
    cudaGetSymbolAddress(&ph1, g_hist1);
    float* xg = (float*)pxg; float* h0 = (float*)ph0; float* h1 = (float*)ph1;

    const int SMEM = 49280 * 4;   // 197120 B
    cudaFuncSetAttribute(rec_kernel, cudaFuncAttributeMaxDynamicSharedMemorySize, SMEM);

    dim3 gg(1024, 8);
    gemm_xg<64,  true ><<<gg, 256>>>(x,  W_ih0, b_ih0, b_hh0, xg);
    reset_bar<<<1, 32>>>();
    rec_kernel<<<128, 256, SMEM>>>(xg, W_hh0, h0);
    gemm_xg<256, false><<<gg, 256>>>(h0, W_ih1, b_ih1, b_hh1, xg);
    reset_bar<<<1, 32>>>();
    rec_kernel<<<128, 256, SMEM>>>(xg, W_hh1, h1);
    head_kernel<<<256, 256>>>(W_head, b_head, out);
}